// round 1
// baseline (speedup 1.0000x reference)
#include <cuda_runtime.h>
#include <math.h>

// Problem constants
#define B 2
#define C 32
#define O 32
#define N 64        // spatial size per dim
#define M 20        // retained modes per dim
#define MM 400      // M*M
#define MMM 8000    // M*M*M
#define NN 4096     // N*N

// Scratch (bss, no allocation)
__device__ float g_Y1[(size_t)B * C * N * N * M];   // 10,485,760  (also reused as U2)
__device__ float g_Y2[(size_t)B * C * N * M * M];   //  3,276,800  (also reused as U1)
__device__ float g_Y3[(size_t)B * C * M * M * M];   //    512,000
__device__ float g_Z [(size_t)B * O * M * M * M];   //    512,000
__device__ float g_Cf[M * N];                       // forward DCT-II matrix [k][n]
__device__ float g_Ci[N * M];                       // inverse DCT-III matrix [n][k]

// ---------------------------------------------------------------------------
// Init: DCT matrices (computed in double, cast to float). Deterministic.
// Cf[k][n] = (k==0) ? 1 : 2*cos(pi*k*(2n+1)/(2N))
// Ci[n][k] = ((k==0) ? 1 : cos(pi*k*(2n+1)/(2N))) / N
// ---------------------------------------------------------------------------
__global__ void init_mats_k() {
    int t = blockIdx.x * blockDim.x + threadIdx.x;
    if (t < M * N) {
        int k = t / N, n = t % N;
        double v = cos(M_PI * (double)k * (double)(2 * n + 1) / (2.0 * N));
        g_Cf[t] = (k == 0) ? 1.0f : (float)(2.0 * v);
    }
    if (t < N * M) {
        int n = t / M, k = t % M;
        double v = cos(M_PI * (double)k * (double)(2 * n + 1) / (2.0 * N));
        g_Ci[t] = (float)(((k == 0) ? 1.0 : v) / (double)N);
    }
}

// ---------------------------------------------------------------------------
// fwd_w: x[b,c,d,h,w] -> Y1[b,c,d,h,kw]   (contract w: 64 -> 20)
// One block per (b,c,d) slice. Tile 64x64 in smem.
// ---------------------------------------------------------------------------
__global__ void fwd_w_k(const float* __restrict__ x) {
    __shared__ float xs[64 * 65];     // [h][w], padded
    __shared__ float cf[M * 65];      // [kw][w], padded
    int slice = blockIdx.x;           // 0..B*C*N-1
    int t = threadIdx.x;              // 256
    const float* xp = x + (size_t)slice * NN;
    for (int i = t; i < NN; i += 256) xs[(i >> 6) * 65 + (i & 63)] = xp[i];
    for (int i = t; i < M * N; i += 256) cf[(i >> 6) * 65 + (i & 63)] = g_Cf[i];
    __syncthreads();
    float* yp = g_Y1 + (size_t)slice * (N * M);
    for (int o = t; o < N * M; o += 256) {
        int h = o / M, kw = o % M;
        const float* xr = &xs[h * 65];
        const float* cr = &cf[kw * 65];
        float acc = 0.f;
#pragma unroll 16
        for (int w = 0; w < N; w++) acc += xr[w] * cr[w];
        yp[o] = acc;
    }
}

// ---------------------------------------------------------------------------
// fwd_h: Y1[b,c,d,h,kw] -> Y2[b,c,d,kh,kw]   (contract h: 64 -> 20)
// One block per (b,c,d). Tile 64x20 in smem.
// ---------------------------------------------------------------------------
__global__ void fwd_h_k() {
    __shared__ float ts[N * M];       // [h][kw]
    __shared__ float cf[M * 65];      // [kh][h], padded
    int slice = blockIdx.x;
    int t = threadIdx.x;              // 256
    const float* p = g_Y1 + (size_t)slice * (N * M);
    for (int i = t; i < N * M; i += 256) ts[i] = p[i];
    for (int i = t; i < M * N; i += 256) cf[(i >> 6) * 65 + (i & 63)] = g_Cf[i];
    __syncthreads();
    float* q = g_Y2 + (size_t)slice * MM;
    for (int o = t; o < MM; o += 256) {
        int kh = o / M, kw = o % M;
        float acc = 0.f;
#pragma unroll 16
        for (int h = 0; h < N; h++) acc += cf[kh * 65 + h] * ts[h * M + kw];
        q[o] = acc;
    }
}

// ---------------------------------------------------------------------------
// fwd_d: Y2[b,c,d,kh,kw] -> Y3[b,c,kd,kh,kw]   (contract d: 64 -> 20)
// Accumulator pattern: one thread per m=(kh,kw), 20 accumulators, loop d.
// grid (B*C, 2), block 200.
// ---------------------------------------------------------------------------
__global__ void fwd_d_k() {
    __shared__ float cf[M * N];
    int bc = blockIdx.x;
    int m = blockIdx.y * 200 + threadIdx.x;   // 0..399
    for (int i = threadIdx.x; i < M * N; i += blockDim.x) cf[i] = g_Cf[i];
    __syncthreads();
    const float* p = g_Y2 + (size_t)bc * (N * MM) + m;
    float acc[M];
#pragma unroll
    for (int k = 0; k < M; k++) acc[k] = 0.f;
    for (int d = 0; d < N; d++) {
        float v = p[(size_t)d * MM];
#pragma unroll
        for (int kd = 0; kd < M; kd++) acc[kd] += cf[kd * N + d] * v;
    }
    float* q = g_Y3 + (size_t)bc * MMM + m;
#pragma unroll
    for (int kd = 0; kd < M; kd++) q[(size_t)kd * MM] = acc[kd];
}

// ---------------------------------------------------------------------------
// mix: Z[b,o,p] = sum_c Y3[b,c,p] * W[c,o,p]   (p = mode triple index, 8000)
// One thread per p, both batches (weight read once). 64 accumulators.
// ---------------------------------------------------------------------------
__global__ void mix_k(const float* __restrict__ w) {
    int m = blockIdx.x * blockDim.x + threadIdx.x;
    if (m >= MMM) return;
    float acc0[O], acc1[O];
#pragma unroll
    for (int o = 0; o < O; o++) { acc0[o] = 0.f; acc1[o] = 0.f; }
    for (int c = 0; c < C; c++) {
        float x0 = g_Y3[(size_t)(0 * C + c) * MMM + m];
        float x1 = g_Y3[(size_t)(1 * C + c) * MMM + m];
        const float* wp = w + (size_t)c * O * MMM + m;
#pragma unroll
        for (int o = 0; o < O; o++) {
            float wv = wp[(size_t)o * MMM];
            acc0[o] += x0 * wv;
            acc1[o] += x1 * wv;
        }
    }
#pragma unroll
    for (int o = 0; o < O; o++) {
        g_Z[(size_t)(0 * O + o) * MMM + m] = acc0[o];
        g_Z[(size_t)(1 * O + o) * MMM + m] = acc1[o];
    }
}

// ---------------------------------------------------------------------------
// inv_d: Z[b,o,kd,m] -> U1[b,o,d,m]  (expand d: 20 -> 64).  U1 lives in g_Y2.
// grid (B*O, 4): each block handles 16 d-values; Z slice (20x400) in smem.
// ---------------------------------------------------------------------------
__global__ void inv_d_k() {
    __shared__ float zs[MMM];         // 20*400 = 8000 floats
    __shared__ float ci[N * M];       // [d][kd]
    int bo = blockIdx.x;
    int d0 = blockIdx.y * 16;
    int t = threadIdx.x;              // 256
    const float* p = g_Z + (size_t)bo * MMM;
    for (int i = t; i < MMM; i += 256) zs[i] = p[i];
    for (int i = t; i < N * M; i += 256) ci[i] = g_Ci[i];
    __syncthreads();
    float* q = g_Y2 + (size_t)bo * (N * MM);
    for (int o = t; o < 16 * MM; o += 256) {
        int d = d0 + o / MM, m = o % MM;
        float acc = 0.f;
#pragma unroll
        for (int kd = 0; kd < M; kd++) acc += ci[d * M + kd] * zs[kd * MM + m];
        q[(size_t)d * MM + m] = acc;
    }
}

// ---------------------------------------------------------------------------
// inv_h: U1[b,o,d,kh,kw] -> U2[b,o,d,h,kw]  (expand h: 20 -> 64). U2 in g_Y1.
// One block per (b,o,d). Tile 20x20 in smem.
// ---------------------------------------------------------------------------
__global__ void inv_h_k() {
    __shared__ float ts[MM];          // [kh][kw]
    __shared__ float ci[N * M];       // [h][kh]
    int s = blockIdx.x;
    int t = threadIdx.x;              // 256
    const float* p = g_Y2 + (size_t)s * MM;
    for (int i = t; i < MM; i += 256) ts[i] = p[i];
    for (int i = t; i < N * M; i += 256) ci[i] = g_Ci[i];
    __syncthreads();
    float* q = g_Y1 + (size_t)s * (N * M);
    for (int o = t; o < N * M; o += 256) {
        int h = o / M, kw = o % M;
        float acc = 0.f;
#pragma unroll
        for (int kh = 0; kh < M; kh++) acc += ci[h * M + kh] * ts[kh * M + kw];
        q[o] = acc;
    }
}

// ---------------------------------------------------------------------------
// inv_w: U2[b,o,d,h,kw] -> out[b,o,d,h,w]  (expand w: 20 -> 64)
// One block per (b,o,d). Tile 64x20 in smem. Ci stored transposed [kw][w]
// to keep consecutive-w lanes on distinct banks.
// ---------------------------------------------------------------------------
__global__ void inv_w_k(float* __restrict__ out) {
    __shared__ float ts[N * M];       // [h][kw]
    __shared__ float cit[M * N];      // [kw][w]  (transposed Ci)
    int s = blockIdx.x;
    int t = threadIdx.x;              // 256
    const float* p = g_Y1 + (size_t)s * (N * M);
    for (int i = t; i < N * M; i += 256) {
        ts[i] = p[i];
        cit[i] = g_Ci[(i & 63) * M + (i >> 6)];   // cit[kw*64+w] = Ci[w][kw]
    }
    __syncthreads();
    float* q = out + (size_t)s * NN;
    for (int o = t; o < NN; o += 256) {
        int h = o >> 6, w = o & 63;
        float acc = 0.f;
#pragma unroll
        for (int kw = 0; kw < M; kw++) acc += cit[kw * N + w] * ts[h * M + kw];
        q[o] = acc;
    }
}

// ---------------------------------------------------------------------------
extern "C" void kernel_launch(void* const* d_in, const int* in_sizes, int n_in,
                              void* d_out, int out_size) {
    const float* x = (const float*)d_in[0];       // (2,32,64,64,64)
    const float* w = (const float*)d_in[1];       // (32,32,20,20,20)
    float* out = (float*)d_out;                   // (2,32,64,64,64)

    init_mats_k<<<5, 256>>>();
    fwd_w_k<<<B * C * N, 256>>>(x);               // 4096 blocks
    fwd_h_k<<<B * C * N, 256>>>();                // 4096 blocks
    {
        dim3 g(B * C, 2);
        fwd_d_k<<<g, 200>>>();
    }
    mix_k<<<(MMM + 255) / 256, 256>>>(w);
    {
        dim3 g(B * O, 4);
        inv_d_k<<<g, 256>>>();
    }
    inv_h_k<<<B * O * N, 256>>>();
    inv_w_k<<<B * O * N, 256>>>(out);
}

// round 2
// speedup vs baseline: 1.5710x; 1.5710x over previous
#include <cuda_runtime.h>
#include <math.h>

#define B 2
#define C 32
#define O 32
#define N 64        // spatial size per dim
#define M 20        // retained modes per dim
#define MM 400
#define MMM 8000
#define NN 4096
#define KP 24       // padded mode count (float4-friendly)

// Scratch (bss, allocation-free)
__device__ float g_Y2[(size_t)B * C * N * MM];   // Y2 [b,c,d,kh,kw]; reused as U1 [b,o,d,kh,kw]
__device__ float g_Y3[(size_t)B * C * MMM];      // [b,c,kd,kh,kw]
__device__ float g_Z [(size_t)B * O * MMM];      // [b,o,kd,kh,kw]
__device__ float g_Cf [M * N];    // forward DCT-II  [k][n]
__device__ float g_CfT[N * KP];   // forward, transposed+padded [n][k]
__device__ float g_Ci [N * M];    // inverse DCT-III [n][k]
__device__ float g_CiT[M * N];    // inverse, transposed [k][n]

// ---------------------------------------------------------------------------
__global__ void init_mats_k() {
    int t = blockIdx.x * blockDim.x + threadIdx.x;
    if (t < M * N) {
        int k = t / N, n = t % N;
        double v = cos(M_PI * (double)k * (double)(2 * n + 1) / (2.0 * N));
        g_Cf[t] = (k == 0) ? 1.0f : (float)(2.0 * v);
        float fi = (float)(((k == 0) ? 1.0 : v) / (double)N);
        g_Ci[n * M + k] = fi;
        g_CiT[k * N + n] = fi;
    }
    if (t < N * KP) {
        int n = t / KP, k = t % KP;
        float f = 0.f;
        if (k < M) {
            double v = cos(M_PI * (double)k * (double)(2 * n + 1) / (2.0 * N));
            f = (k == 0) ? 1.0f : (float)(2.0 * v);
        }
        g_CfT[t] = f;
    }
}

// ---------------------------------------------------------------------------
// fwd_wh: x[b,c,d,h,w] -> Y2[b,c,d,kh,kw]  (fused w- and h-contractions)
// One block per (b,c,d) slice.
// ---------------------------------------------------------------------------
__global__ __launch_bounds__(256) void fwd_wh_k(const float* __restrict__ x) {
    __shared__ float xs[64 * 65];     // [h][w] padded
    __shared__ float cft[64 * KP];    // [w][kw] padded
    __shared__ float cfs[M * 64];     // [kh][h]
    __shared__ float tmp[64 * KP];    // [h][kw] padded
    int slice = blockIdx.x;
    int t = threadIdx.x;
    const float* xp = x + (size_t)slice * NN;
    for (int i = t * 4; i < NN; i += 256 * 4) {
        float4 v = *(const float4*)(xp + i);
        int h = i >> 6, w = i & 63;
        float* dst = &xs[h * 65 + w];
        dst[0] = v.x; dst[1] = v.y; dst[2] = v.z; dst[3] = v.w;
    }
    for (int i = t; i < 64 * KP; i += 256) cft[i] = g_CfT[i];
    for (int i = t; i < M * 64; i += 256) cfs[i] = g_Cf[i];
    __syncthreads();
    // stage 1: tmp[h][kw] = sum_w xs[h][w] * cft[w][kw]
    if (t < 192) {
        int h = t / 3, kw0 = (t % 3) * 8;
        float a[8];
#pragma unroll
        for (int j = 0; j < 8; j++) a[j] = 0.f;
        const float* xr = &xs[h * 65];
#pragma unroll 4
        for (int w = 0; w < 64; w++) {
            float xv = xr[w];
            float4 c0 = *(const float4*)&cft[w * KP + kw0];
            float4 c1 = *(const float4*)&cft[w * KP + kw0 + 4];
            a[0] += xv * c0.x; a[1] += xv * c0.y; a[2] += xv * c0.z; a[3] += xv * c0.w;
            a[4] += xv * c1.x; a[5] += xv * c1.y; a[6] += xv * c1.z; a[7] += xv * c1.w;
        }
        float* tr = &tmp[h * KP + kw0];
#pragma unroll
        for (int j = 0; j < 8; j++) tr[j] = a[j];
    }
    __syncthreads();
    // stage 2: Y2[kh][kw] = sum_h cfs[kh][h] * tmp[h][kw]
    if (t < 100) {
        int kh = t / 5, kw0 = (t % 5) * 4;
        float4 a = make_float4(0.f, 0.f, 0.f, 0.f);
        const float* cr = &cfs[kh * 64];
#pragma unroll 8
        for (int h = 0; h < 64; h++) {
            float cv = cr[h];
            float4 tv = *(const float4*)&tmp[h * KP + kw0];
            a.x += cv * tv.x; a.y += cv * tv.y; a.z += cv * tv.z; a.w += cv * tv.w;
        }
        *(float4*)(g_Y2 + (size_t)slice * MM + kh * 20 + kw0) = a;
    }
}

// ---------------------------------------------------------------------------
// fwd_d: Y2[bc,d,m] -> Y3[bc,kd,m]  (contract d 64->20), m-tiled.
// grid (B*C, 4), tile of 100 m.
// ---------------------------------------------------------------------------
__global__ __launch_bounds__(256) void fwd_d_k() {
    __shared__ float slab[64 * 104];  // [d][m] padded
    __shared__ float cfs[M * 64];     // [kd][d]
    int bc = blockIdx.x;
    int m0 = blockIdx.y * 100;
    int t = threadIdx.x;
    const float* p = g_Y2 + (size_t)bc * (N * MM) + m0;
    for (int i = t; i < 64 * 25; i += 256) {
        int d = i / 25, j = (i % 25) * 4;
        *(float4*)&slab[d * 104 + j] = *(const float4*)(p + (size_t)d * MM + j);
    }
    for (int i = t; i < M * 64; i += 256) cfs[i] = g_Cf[i];
    __syncthreads();
    if (t < 250) {
        int kd0 = (t / 25) * 2, m = (t % 25) * 4;
        float4 a0 = make_float4(0.f, 0.f, 0.f, 0.f);
        float4 a1 = make_float4(0.f, 0.f, 0.f, 0.f);
#pragma unroll 4
        for (int d = 0; d < 64; d++) {
            float4 v = *(const float4*)&slab[d * 104 + m];
            float c0 = cfs[kd0 * 64 + d], c1 = cfs[(kd0 + 1) * 64 + d];
            a0.x += c0 * v.x; a0.y += c0 * v.y; a0.z += c0 * v.z; a0.w += c0 * v.w;
            a1.x += c1 * v.x; a1.y += c1 * v.y; a1.z += c1 * v.z; a1.w += c1 * v.w;
        }
        float* q = g_Y3 + (size_t)bc * MMM + m0 + m;
        *(float4*)(q + (size_t)kd0 * MM) = a0;
        *(float4*)(q + (size_t)(kd0 + 1) * MM) = a1;
    }
}

// ---------------------------------------------------------------------------
// mix: Z[b,o,p] = sum_c Y3[b,c,p] * W[c,o,p].  grid 250 (m-tiles of 32).
// Warp spans m -> weight LDG fully coalesced; each weight read once.
// ---------------------------------------------------------------------------
__global__ __launch_bounds__(256) void mix_k(const float* __restrict__ w) {
    __shared__ float ys[2 * C * 32];  // [b][c][ml]
    int m0 = blockIdx.x * 32;
    int t = threadIdx.x;
    for (int i = t; i < 2 * C * 32; i += 256) {
        int b = i / (C * 32), c = (i / 32) % C, ml = i % 32;
        ys[i] = g_Y3[(size_t)(b * C + c) * MMM + m0 + ml];
    }
    __syncthreads();
    int ml = t & 31, og = t >> 5;     // 8 o-groups of 4
    float a[4][2];
#pragma unroll
    for (int i = 0; i < 4; i++) { a[i][0] = 0.f; a[i][1] = 0.f; }
    for (int c = 0; c < C; c++) {
        float y0 = ys[c * 32 + ml];
        float y1 = ys[(C + c) * 32 + ml];
        const float* wp = w + ((size_t)c * O + og * 4) * MMM + m0 + ml;
#pragma unroll
        for (int oi = 0; oi < 4; oi++) {
            float wv = wp[(size_t)oi * MMM];
            a[oi][0] += y0 * wv;
            a[oi][1] += y1 * wv;
        }
    }
#pragma unroll
    for (int oi = 0; oi < 4; oi++) {
        int o = og * 4 + oi;
        g_Z[(size_t)o * MMM + m0 + ml] = a[oi][0];
        g_Z[(size_t)(O + o) * MMM + m0 + ml] = a[oi][1];
    }
}

// ---------------------------------------------------------------------------
// inv_d: Z[bo,kd,m] -> U1[bo,d,m] (expand d 20->64). grid (B*O, 4).
// ---------------------------------------------------------------------------
__global__ __launch_bounds__(256) void inv_d_k() {
    __shared__ float zs[MMM];        // [kd][m]
    __shared__ float cis[N * M];     // [d][kd]
    int bo = blockIdx.x;
    int d0 = blockIdx.y * 16;
    int t = threadIdx.x;
    const float* p = g_Z + (size_t)bo * MMM;
    for (int i = t; i < MMM / 4; i += 256)
        *(float4*)&zs[i * 4] = *(const float4*)(p + i * 4);
    for (int i = t; i < N * M; i += 256) cis[i] = g_Ci[i];
    __syncthreads();
    float* q = g_Y2 + (size_t)bo * (N * MM);
    for (int slot = t; slot < 800; slot += 256) {
        int d = d0 + (slot / 100) * 2;
        int m = (slot % 100) * 4;
        float4 a0 = make_float4(0.f, 0.f, 0.f, 0.f);
        float4 a1 = make_float4(0.f, 0.f, 0.f, 0.f);
#pragma unroll
        for (int kd = 0; kd < M; kd++) {
            float4 v = *(const float4*)&zs[kd * MM + m];
            float c0 = cis[d * M + kd], c1 = cis[(d + 1) * M + kd];
            a0.x += c0 * v.x; a0.y += c0 * v.y; a0.z += c0 * v.z; a0.w += c0 * v.w;
            a1.x += c1 * v.x; a1.y += c1 * v.y; a1.z += c1 * v.z; a1.w += c1 * v.w;
        }
        *(float4*)(q + (size_t)d * MM + m) = a0;
        *(float4*)(q + (size_t)(d + 1) * MM + m) = a1;
    }
}

// ---------------------------------------------------------------------------
// inv_hw: U1[b,o,d,kh,kw] -> out[b,o,d,h,w]  (fused h- and w-expansions)
// One block per (b,o,d) slice.
// ---------------------------------------------------------------------------
__global__ __launch_bounds__(256) void inv_hw_k(float* __restrict__ out) {
    __shared__ float zs[MM];          // [kh][kw]
    __shared__ float cis[64 * M];     // [h][kh]
    __shared__ float cit[M * 64];     // [kw][w]
    __shared__ float tmp[64 * KP];    // [h][kw] padded
    int slice = blockIdx.x;
    int t = threadIdx.x;
    const float* p = g_Y2 + (size_t)slice * MM;
    for (int i = t; i < MM; i += 256) zs[i] = p[i];
    for (int i = t; i < 64 * M; i += 256) { cis[i] = g_Ci[i]; cit[i] = g_CiT[i]; }
    __syncthreads();
    // stage 1: tmp[h][kw] = sum_kh cis[h][kh] * zs[kh][kw]
    for (int slot = t; slot < 320; slot += 256) {
        int h = slot / 5, kw0 = (slot % 5) * 4;
        float4 a = make_float4(0.f, 0.f, 0.f, 0.f);
        const float* cr = &cis[h * M];
#pragma unroll
        for (int kh = 0; kh < M; kh++) {
            float c = cr[kh];
            float4 z = *(const float4*)&zs[kh * M + kw0];
            a.x += c * z.x; a.y += c * z.y; a.z += c * z.z; a.w += c * z.w;
        }
        *(float4*)&tmp[h * KP + kw0] = a;
    }
    __syncthreads();
    // stage 2: out[h][w] = sum_kw tmp[h][kw] * cit[kw][w]; 16 outputs/thread
    int h = t >> 2, w0 = (t & 3) * 16;
    float4 a[4];
#pragma unroll
    for (int j = 0; j < 4; j++) a[j] = make_float4(0.f, 0.f, 0.f, 0.f);
    const float* tr = &tmp[h * KP];
#pragma unroll
    for (int kw = 0; kw < M; kw++) {
        float tv = tr[kw];
        const float* cr = &cit[kw * 64 + w0];
#pragma unroll
        for (int j = 0; j < 4; j++) {
            float4 cv = *(const float4*)(cr + j * 4);
            a[j].x += tv * cv.x; a[j].y += tv * cv.y; a[j].z += tv * cv.z; a[j].w += tv * cv.w;
        }
    }
    float* q = out + (size_t)slice * NN + h * 64 + w0;
#pragma unroll
    for (int j = 0; j < 4; j++) *(float4*)(q + j * 4) = a[j];
}

// ---------------------------------------------------------------------------
extern "C" void kernel_launch(void* const* d_in, const int* in_sizes, int n_in,
                              void* d_out, int out_size) {
    const float* x = (const float*)d_in[0];       // (2,32,64,64,64)
    const float* w = (const float*)d_in[1];       // (32,32,20,20,20)
    float* out = (float*)d_out;                   // (2,32,64,64,64)

    init_mats_k<<<6, 256>>>();
    fwd_wh_k<<<B * C * N, 256>>>(x);              // 4096 blocks
    {
        dim3 g(B * C, 4);
        fwd_d_k<<<g, 256>>>();                    // 256 blocks
    }
    mix_k<<<250, 256>>>(w);                       // 250 blocks
    {
        dim3 g(B * O, 4);
        inv_d_k<<<g, 256>>>();                    // 256 blocks
    }
    inv_hw_k<<<B * O * N, 256>>>(out);            // 4096 blocks
}

// round 3
// speedup vs baseline: 2.2396x; 1.4256x over previous
#include <cuda_runtime.h>

#define B 2
#define C 32
#define O 32
#define N 64
#define M 20
#define MM 400
#define MMM 8000
#define NN 4096

// Scratch (bss, allocation-free)
__device__ float g_Y2[(size_t)B * C * N * MM];   // fwd Y2 [bc][d][kh*20+kw]; reused as U1 [bo][d][m]
__device__ float g_Y3[(size_t)B * C * MMM];      // [bc][kd][m]
__device__ float g_Z [(size_t)B * O * MMM];      // [bo][kd][m]
__device__ float g_cf [N * M];                   // runtime fwd table  [n][k]
__device__ float g_ciT[M * N];                   // runtime inv table  [k][n]

// ---------------------------------------------------------------------------
// Compile-time DCT coefficients (Taylor cos, folded to FFMA immediates)
// ---------------------------------------------------------------------------
__host__ __device__ constexpr double tcos(int a) {      // cos(pi*a/128), 0<=a<=128
    double x = 3.14159265358979323846264338327950288 * (double)a / 128.0;
    double x2 = x * x, term = 1.0, s = 1.0;
    for (int i = 1; i <= 16; i++) { term *= -x2 / (double)((2 * i - 1) * (2 * i)); s += term; }
    return s;
}
__host__ __device__ constexpr int redu(int k, int n) {
    int a = (k * (2 * n + 1)) % 256;
    return (a > 128) ? 256 - a : a;
}
__host__ __device__ constexpr float CF(int n, int k) {  // forward DCT-II coeff
    double c = tcos(redu(k, n));
    return (k == 0) ? 1.0f : (float)(2.0 * c);
}
__host__ __device__ constexpr float CI(int n, int k) {  // inverse DCT-III coeff
    double c = tcos(redu(k, n));
    return (float)(((k == 0) ? 1.0 : c) / 64.0);
}

// static_for with genuine compile-time index
template<int I> struct ic { static constexpr int value = I; };
template<int I, int Nn> struct SF {
    template<class F> __device__ __forceinline__ static void run(F&& f) {
        f(ic<I>{}); SF<I + 1, Nn>::run(f);
    }
};
template<int Nn> struct SF<Nn, Nn> {
    template<class F> __device__ __forceinline__ static void run(F&&) {}
};
template<int Nn, class F> __device__ __forceinline__ void static_for(F&& f) { SF<0, Nn>::run(f); }

// ---------------------------------------------------------------------------
__global__ void init_mats_k() {
    int t = blockIdx.x * blockDim.x + threadIdx.x;
    if (t < N * M) {
        int n = t / M, k = t % M;
        g_cf[t] = CF(n, k);
        int k2 = t / N, n2 = t % N;
        g_ciT[t] = CI(n2, k2);
    }
}

// ---------------------------------------------------------------------------
// fwd_wh: x[slice][h][w] -> Y2[slice][kh][kw], 2 slices per block
// ---------------------------------------------------------------------------
template<int KW0>
__device__ __forceinline__ void fwd_s1(const float* __restrict__ xr, float* __restrict__ tp) {
    float acc[10];
#pragma unroll
    for (int k = 0; k < 10; k++) acc[k] = 0.f;
    static_for<16>([&](auto W4) {
        constexpr int w4 = W4.value;
        float4 xv = *(const float4*)(xr + w4 * 4);
        static_for<10>([&](auto K) {
            constexpr int k = K.value;
            constexpr float c0 = CF(w4 * 4 + 0, KW0 + k);
            constexpr float c1 = CF(w4 * 4 + 1, KW0 + k);
            constexpr float c2 = CF(w4 * 4 + 2, KW0 + k);
            constexpr float c3 = CF(w4 * 4 + 3, KW0 + k);
            acc[k] += xv.x * c0; acc[k] += xv.y * c1;
            acc[k] += xv.z * c2; acc[k] += xv.w * c3;
        });
    });
#pragma unroll
    for (int k = 0; k < 10; k++) tp[KW0 + k] = acc[k];
}

template<int KH0>
__device__ __forceinline__ void fwd_s2(const float* __restrict__ tcol, float* __restrict__ outp, bool act) {
    float acc[5] = {0.f, 0.f, 0.f, 0.f, 0.f};
    static_for<64>([&](auto H) {
        constexpr int h = H.value;
        float tv = tcol[h * 21];
        static_for<5>([&](auto K) {
            constexpr int k = K.value;
            constexpr float c = CF(h, KH0 + k);
            acc[k] += tv * c;
        });
    });
    if (act) {
#pragma unroll
        for (int k = 0; k < 5; k++) outp[(KH0 + k) * 20] = acc[k];
    }
}

__global__ __launch_bounds__(256) void fwd_wh_k(const float* __restrict__ x) {
    __shared__ float xs[2][64 * 68];
    __shared__ float tmp[2][64 * 21];
    int t = threadIdx.x, wid = t >> 5, lane = t & 31;
    int sl = wid >> 2, ws = wid & 3;
    int slice = blockIdx.x * 2 + sl;
    const float* xp = x + (size_t)slice * NN;
    int t2 = t & 127;
#pragma unroll
    for (int r = 0; r < 8; r++) {
        int idx = t2 + r * 128;                 // float4 index 0..1023
        int h = idx >> 4, w4 = idx & 15;
        *(float4*)&xs[sl][h * 68 + w4 * 4] = *(const float4*)(xp + idx * 4);
    }
    __syncthreads();
    {   // stage 1: tmp[h][kw] = sum_w xs[h][w]*CF(w,kw)
        int h = (ws >> 1) * 32 + lane;
        const float* xr = &xs[sl][h * 68];
        float* tp = &tmp[sl][h * 21];
        if (ws & 1) fwd_s1<10>(xr, tp); else fwd_s1<0>(xr, tp);
    }
    __syncthreads();
    {   // stage 2: Y2[kh][kw] = sum_h CF(h,kh)*tmp[h][kw]
        bool act = lane < 20;
        int kwc = act ? lane : 0;
        const float* tcol = &tmp[sl][kwc];
        float* outp = g_Y2 + (size_t)slice * MM + kwc;
        switch (ws) {
            case 0: fwd_s2<0>(tcol, outp, act); break;
            case 1: fwd_s2<5>(tcol, outp, act); break;
            case 2: fwd_s2<10>(tcol, outp, act); break;
            default: fwd_s2<15>(tcol, outp, act); break;
        }
    }
}

// ---------------------------------------------------------------------------
// fwd_d: Y2[bc][d][m] -> Y3[bc][kd][m]   grid (64 bc, 4 mtile), block 64
// ---------------------------------------------------------------------------
__global__ __launch_bounds__(64) void fwd_d_k() {
    __shared__ float ys2[64 * 100];
    __shared__ float cfs[N * M];
    int bc = blockIdx.x, mt = blockIdx.y;
    int t = threadIdx.x, wid = t >> 5, lane = t & 31;
    const float* src = g_Y2 + (size_t)bc * (N * MM) + mt * 100;
    for (int i = t; i < 1600; i += 64) {
        int d = i / 25, j = (i % 25) * 4;
        *(float4*)&ys2[d * 100 + j] = *(const float4*)(src + (size_t)d * MM + j);
    }
    for (int i = t; i < N * M; i += 64) cfs[i] = g_cf[i];
    __syncthreads();
    int KD0 = wid * 10;
    bool act = lane < 25;
    int ml = act ? lane * 4 : 0;
    float4 acc[10];
#pragma unroll
    for (int k = 0; k < 10; k++) acc[k] = make_float4(0.f, 0.f, 0.f, 0.f);
#pragma unroll 4
    for (int d = 0; d < 64; d++) {
        float4 v = *(const float4*)&ys2[d * 100 + ml];
#pragma unroll
        for (int k = 0; k < 10; k++) {
            float cc = cfs[d * 20 + KD0 + k];
            acc[k].x += cc * v.x; acc[k].y += cc * v.y;
            acc[k].z += cc * v.z; acc[k].w += cc * v.w;
        }
    }
    if (act) {
        float* q = g_Y3 + (size_t)bc * MMM + mt * 100 + lane * 4;
#pragma unroll
        for (int k = 0; k < 10; k++) *(float4*)(q + (size_t)(KD0 + k) * MM) = acc[k];
    }
}

// ---------------------------------------------------------------------------
// mix: Z[b,o,m] = sum_c Y3[b,c,m]*W[c,o,m]   grid (63 mtiles of 128, 2 o-half)
// ---------------------------------------------------------------------------
__global__ __launch_bounds__(256) void mix_k(const float* __restrict__ w) {
    __shared__ float ys[2 * C * 128];
    int mbase = blockIdx.x * 128, oy = blockIdx.y;
    int t = threadIdx.x;
    for (int i = t; i < 2 * C * 128; i += 256) {
        int b = i >> 12, c = (i >> 7) & 31, ml = i & 127;
        int m = mbase + ml;
        ys[i] = (m < MMM) ? g_Y3[(size_t)(b * C + c) * MMM + m] : 0.f;
    }
    __syncthreads();
    int wid = t >> 5, lane = t & 31;
    int o0 = oy * 16 + wid * 2;
    int m0 = mbase + lane * 4;
    bool valid = m0 < MMM;
    float4 a00 = make_float4(0.f,0.f,0.f,0.f), a01 = a00, a10 = a00, a11 = a00;
    const float* y0b = &ys[lane * 4];
    const float* y1b = &ys[C * 128 + lane * 4];
#pragma unroll 4
    for (int c = 0; c < C; c++) {
        float4 w0 = make_float4(0.f,0.f,0.f,0.f), w1 = w0;
        if (valid) {
            w0 = *(const float4*)(w + ((size_t)c * O + o0) * MMM + m0);
            w1 = *(const float4*)(w + ((size_t)c * O + o0 + 1) * MMM + m0);
        }
        float4 y0 = *(const float4*)(y0b + c * 128);
        float4 y1 = *(const float4*)(y1b + c * 128);
        a00.x += y0.x*w0.x; a00.y += y0.y*w0.y; a00.z += y0.z*w0.z; a00.w += y0.w*w0.w;
        a01.x += y1.x*w0.x; a01.y += y1.y*w0.y; a01.z += y1.z*w0.z; a01.w += y1.w*w0.w;
        a10.x += y0.x*w1.x; a10.y += y0.y*w1.y; a10.z += y0.z*w1.z; a10.w += y0.w*w1.w;
        a11.x += y1.x*w1.x; a11.y += y1.y*w1.y; a11.z += y1.z*w1.z; a11.w += y1.w*w1.w;
    }
    if (valid) {
        *(float4*)(g_Z + (size_t)o0 * MMM + m0) = a00;
        *(float4*)(g_Z + (size_t)(O + o0) * MMM + m0) = a01;
        *(float4*)(g_Z + (size_t)(o0 + 1) * MMM + m0) = a10;
        *(float4*)(g_Z + (size_t)(O + o0 + 1) * MMM + m0) = a11;
    }
}

// ---------------------------------------------------------------------------
// inv_d: Z[bo][kd][m] -> U1[bo][d][m] (into g_Y2)  grid (64 bo, 4 dquarter)
// ---------------------------------------------------------------------------
__global__ __launch_bounds__(256) void inv_d_k() {
    __shared__ float zs[MMM];
    __shared__ float cis[M * N];      // [kd][d]
    int bo = blockIdx.x;
    int t = threadIdx.x, wid = t >> 5, lane = t & 31;
    const float* p = g_Z + (size_t)bo * MMM;
    for (int i = t; i < MMM / 4; i += 256)
        *(float4*)&zs[i * 4] = *(const float4*)(p + i * 4);
    for (int i = t; i < M * N; i += 256) cis[i] = g_ciT[i];
    __syncthreads();
    int mt = wid & 3;
    int d0 = blockIdx.y * 16 + (wid >> 2) * 8;
    bool act = lane < 25;
    int ml = act ? lane * 4 : 0;
    int m0 = mt * 100 + ml;
    float4 acc[8];
#pragma unroll
    for (int i = 0; i < 8; i++) acc[i] = make_float4(0.f,0.f,0.f,0.f);
#pragma unroll
    for (int kd = 0; kd < M; kd++) {
        float4 v = *(const float4*)&zs[kd * MM + m0];
        float4 c0 = *(const float4*)&cis[kd * N + d0];
        float4 c1 = *(const float4*)&cis[kd * N + d0 + 4];
        acc[0].x += c0.x*v.x; acc[0].y += c0.x*v.y; acc[0].z += c0.x*v.z; acc[0].w += c0.x*v.w;
        acc[1].x += c0.y*v.x; acc[1].y += c0.y*v.y; acc[1].z += c0.y*v.z; acc[1].w += c0.y*v.w;
        acc[2].x += c0.z*v.x; acc[2].y += c0.z*v.y; acc[2].z += c0.z*v.z; acc[2].w += c0.z*v.w;
        acc[3].x += c0.w*v.x; acc[3].y += c0.w*v.y; acc[3].z += c0.w*v.z; acc[3].w += c0.w*v.w;
        acc[4].x += c1.x*v.x; acc[4].y += c1.x*v.y; acc[4].z += c1.x*v.z; acc[4].w += c1.x*v.w;
        acc[5].x += c1.y*v.x; acc[5].y += c1.y*v.y; acc[5].z += c1.y*v.z; acc[5].w += c1.y*v.w;
        acc[6].x += c1.z*v.x; acc[6].y += c1.z*v.y; acc[6].z += c1.z*v.z; acc[6].w += c1.z*v.w;
        acc[7].x += c1.w*v.x; acc[7].y += c1.w*v.y; acc[7].z += c1.w*v.z; acc[7].w += c1.w*v.w;
    }
    if (act) {
        float* q = g_Y2 + (size_t)bo * (N * MM) + m0;
#pragma unroll
        for (int i = 0; i < 8; i++) *(float4*)(q + (size_t)(d0 + i) * MM) = acc[i];
    }
}

// ---------------------------------------------------------------------------
// inv_hw: U1[slice][kh][kw] -> out[slice][h][w], 2 slices per block
// ---------------------------------------------------------------------------
template<int HB>
__device__ __forceinline__ void inv_s1(const float* __restrict__ zcol, float* __restrict__ tcol, bool act) {
    float acc[16];
#pragma unroll
    for (int i = 0; i < 16; i++) acc[i] = 0.f;
    static_for<20>([&](auto KH) {
        constexpr int kh = KH.value;
        float zv = zcol[kh * 20];
        static_for<16>([&](auto I) {
            constexpr int i = I.value;
            constexpr float c = CI(HB + i, kh);
            acc[i] += zv * c;
        });
    });
    if (act) {
#pragma unroll
        for (int i = 0; i < 16; i++) tcol[(HB + i) * 21] = acc[i];
    }
}

template<int W0>
__device__ __forceinline__ void inv_s2(const float* __restrict__ trow, float* __restrict__ orow) {
    float acc[32];
#pragma unroll
    for (int i = 0; i < 32; i++) acc[i] = 0.f;
    static_for<20>([&](auto KW) {
        constexpr int kw = KW.value;
        float tv = trow[kw];
        static_for<32>([&](auto I) {
            constexpr int i = I.value;
            constexpr float c = CI(W0 + i, kw);
            acc[i] += tv * c;
        });
    });
#pragma unroll
    for (int i = 0; i < 32; i++) orow[W0 + i] = acc[i];
}

__global__ __launch_bounds__(256) void inv_hw_k(float* __restrict__ out) {
    __shared__ float zs[2][MM];
    __shared__ float tmp[2][64 * 21];
    __shared__ float ob[2][64 * 65];
    int t = threadIdx.x, wid = t >> 5, lane = t & 31;
    int sl = wid >> 2, ws = wid & 3;
    int slice = blockIdx.x * 2 + sl;
    int t2 = t & 127;
    const float* p = g_Y2 + (size_t)slice * MM;
    for (int i = t2; i < MM; i += 128) zs[sl][i] = p[i];
    __syncthreads();
    {   // stage 1: tmp[h][kw] = sum_kh CI(h,kh)*zs[kh][kw]
        bool act = lane < 20;
        int kwc = act ? lane : 0;
        const float* zcol = &zs[sl][kwc];
        float* tcol = &tmp[sl][kwc];
        switch (ws) {
            case 0: inv_s1<0>(zcol, tcol, act); break;
            case 1: inv_s1<16>(zcol, tcol, act); break;
            case 2: inv_s1<32>(zcol, tcol, act); break;
            default: inv_s1<48>(zcol, tcol, act); break;
        }
    }
    __syncthreads();
    {   // stage 2: ob[h][w] = sum_kw tmp[h][kw]*CI(w,kw)
        int h = (ws & 1) * 32 + lane;
        const float* trow = &tmp[sl][h * 21];
        float* orow = &ob[sl][h * 65];
        if (ws >> 1) inv_s2<32>(trow, orow); else inv_s2<0>(trow, orow);
    }
    __syncthreads();
    float* q = out + (size_t)slice * NN;
    for (int i = t2; i < NN; i += 128) {
        int h = i >> 6, w = i & 63;
        q[i] = ob[sl][h * 65 + w];
    }
}

// ---------------------------------------------------------------------------
extern "C" void kernel_launch(void* const* d_in, const int* in_sizes, int n_in,
                              void* d_out, int out_size) {
    const float* x = (const float*)d_in[0];       // (2,32,64,64,64)
    const float* w = (const float*)d_in[1];       // (32,32,20,20,20)
    float* out = (float*)d_out;                   // (2,32,64,64,64)

    init_mats_k<<<5, 256>>>();
    fwd_wh_k<<<B * C * N / 2, 256>>>(x);          // 2048 blocks
    {
        dim3 g(B * C, 4);
        fwd_d_k<<<g, 64>>>();                     // 256 blocks
    }
    {
        dim3 g(63, 2);
        mix_k<<<g, 256>>>(w);                     // 126 blocks
    }
    {
        dim3 g(B * O, 4);
        inv_d_k<<<g, 256>>>();                    // 256 blocks
    }
    inv_hw_k<<<B * O * N / 2, 256>>>(out);        // 2048 blocks
}